// round 10
// baseline (speedup 1.0000x reference)
#include <cuda_runtime.h>
#include <cuda_bf16.h>
#include <math.h>
#include <cstdint>

// Problem constants
#define KB   8      // batch
#define KN   1024   // sequence length
#define KD   512    // model dim
#define KH   8      // heads
#define KDH  64     // dim per head
#define KQ   1536   // qkv columns

typedef __nv_bfloat16 bf16;
typedef __nv_bfloat162 bf162;

// ---------------------------------------------------------------------------
// Scratch (static __device__ arrays; allocation-free per harness rules)
// ---------------------------------------------------------------------------
__device__ __align__(16) bf16  g_xh [KB * KN * KD];           // x split hi
__device__ __align__(16) bf16  g_xl [KB * KN * KD];           // x split lo
__device__ __align__(16) bf16  g_wqh[KQ * KD];                // w_qkv^T hi
__device__ __align__(16) bf16  g_wql[KQ * KD];
__device__ __align__(16) bf16  g_woh[KD * KD];                // w_out^T hi
__device__ __align__(16) bf16  g_wol[KD * KD];
__device__ __align__(16) bf16  g_qkvh[KB * KN * KQ];          // qkv split hi
__device__ __align__(16) bf16  g_qkvl[KB * KN * KQ];
__device__ __align__(16) float g_attn[KB * KH * KN * KN];     // raw logits (fp32)
__device__ __align__(16) bf16  g_ch [KB * KH * KN * KN];      // C = conv-mix, hi
__device__ __align__(16) bf16  g_cl [KB * KH * KN * KN];      // C lo
__device__ __align__(16) bf16  g_vth[KB * KH * KDH * KN];     // V^T [bh, d, m] hi
__device__ __align__(16) bf16  g_vtl[KB * KH * KDH * KN];
__device__ __align__(16) float g_u  [KB * KH * KN * KDH];     // U = C @ V (fp32)
__device__ __align__(16) bf16  g_yh [KB * KN * KD];           // Y split hi
__device__ __align__(16) bf16  g_yl [KB * KN * KD];
__device__ __align__(16) float g_vsum[KB * KH * KDH];
__device__ __align__(16) float g_part[KB * KN * 36];
__device__ __align__(16) float g_S  [36];
__device__ float g_k0[KH];
__device__ float g_k1[KH];

// ---------------------------------------------------------------------------
// Helpers
// ---------------------------------------------------------------------------
__device__ __forceinline__ uint32_t smem_u32(const void* p) {
    uint32_t a;
    asm("{ .reg .u64 t; cvta.to.shared.u64 t, %1; cvt.u32.u64 %0, t; }"
        : "=r"(a) : "l"(p));
    return a;
}
#define SW128(x) ((x) ^ (((x) >> 3) & 0x70))

__device__ __forceinline__ void split_bf(float v, bf16& h, bf16& l) {
    h = __float2bfloat16(v);
    l = __float2bfloat16(v - __bfloat162float(h));
}

// ldmatrix x4 (b16)
__device__ __forceinline__ void ldsm4(uint32_t addr, uint32_t* r) {
    asm volatile("ldmatrix.sync.aligned.m8n8.x4.shared.b16 {%0,%1,%2,%3}, [%4];"
                 : "=r"(r[0]), "=r"(r[1]), "=r"(r[2]), "=r"(r[3]) : "r"(addr));
}
// mma m16n8k16 bf16 -> f32 accumulate
__device__ __forceinline__ void mma16816(float* c, const uint32_t* a,
                                         uint32_t b0, uint32_t b1) {
    asm volatile(
        "mma.sync.aligned.m16n8k16.row.col.f32.bf16.bf16.f32 "
        "{%0,%1,%2,%3}, {%4,%5,%6,%7}, {%8,%9}, {%0,%1,%2,%3};"
        : "+f"(c[0]), "+f"(c[1]), "+f"(c[2]), "+f"(c[3])
        : "r"(a[0]), "r"(a[1]), "r"(a[2]), "r"(a[3]), "r"(b0), "r"(b1));
}
// 16-byte async copy global -> shared
__device__ __forceinline__ void cpasync16(uint32_t s, const void* g) {
    asm volatile("cp.async.cg.shared.global [%0], [%1], 16;"
                 :: "r"(s), "l"(g));
}
#define CP_COMMIT()  asm volatile("cp.async.commit_group;" ::: "memory")
#define CP_WAIT0()   asm volatile("cp.async.wait_group 0;" ::: "memory")
#define CP_WAIT1()   asm volatile("cp.async.wait_group 1;" ::: "memory")

// ---------------------------------------------------------------------------
// bf16x2-split GEMM with 2-stage cp.async pipeline + fragment double-buffer.
//   D[128 x BN] = alpha * A @ B^T (+bias)
//   A rows K-major (bf16 hi/lo), B rows K-major (B[n][k]). K multiple of 64.
//   MODE 0: fp32 out *alpha; 1: fp32 *alpha + bias; 2: bf16 hi/lo pair out.
// ---------------------------------------------------------------------------
template <int BN, int MODE>
__global__ __launch_bounds__(256, 1)
void tc_gemm(const bf16* __restrict__ Ah, const bf16* __restrict__ Al,
             const bf16* __restrict__ Bh, const bf16* __restrict__ Bl,
             float* __restrict__ Cf, bf16* __restrict__ Ch,
             bf16* __restrict__ Cl, const float* __restrict__ bias,
             int K, int lda, int ldb, int ldc,
             int HB, long sA1, long sA2, long sB1, long sB2,
             long sC1, long sC2, float alpha)
{
    extern __shared__ __align__(1024) char smem[];
    constexpr int STAGE = 32768 + BN * 256;   // AH(16K)+AL(16K)+BH+BL
    constexpr int OFF0  = 1024;

    const uint32_t sb = smem_u32(smem);
    const int tid = threadIdx.x, wid = tid >> 5, lane = tid & 31;
    const int z = blockIdx.z;
    const long zq = z / HB, zr = z % HB;
    const bf16* pAh = Ah + zq * sA1 + zr * sA2;
    const bf16* pAl = Al + zq * sA1 + zr * sA2;
    const bf16* pBh = Bh + zq * sB1 + zr * sB2;
    const bf16* pBl = Bl + zq * sB1 + zr * sB2;
    const int row0 = blockIdx.y * 128;
    const int col0 = blockIdx.x * BN;
    const int nch = K >> 6;

    constexpr int WNT = BN / 2;          // warp n-tile width (64 or 32)
    constexpr int NI  = WNT / 8;         // n 16x8 tiles per warp
    constexpr int NPT = WNT / 16;        // ldmatrix.x4 pairs per warp
    const int wr = wid & 3;              // row group (32 rows)
    const int wc = wid >> 2;             // col group

    float acc[2][NI][4];
#pragma unroll
    for (int mi = 0; mi < 2; mi++)
#pragma unroll
        for (int ni = 0; ni < NI; ni++)
#pragma unroll
            for (int e = 0; e < 4; e++) acc[mi][ni][e] = 0.f;

    const int arow = lane & 15;
    const int akb  = (lane >> 4) << 4;
    const int brow = ((lane >> 4) << 3) + (lane & 7);
    const int bkb  = ((lane >> 3) & 1) << 4;

    // --- async stage loader: chunk ch -> stage st ---
    auto issue_chunk = [&](int st, int ch) {
        const int kt = ch << 6;
        const uint32_t base = sb + OFF0 + st * STAGE;
        for (int i = tid; i < 128 * 8; i += 256) {
            int r = i >> 3, c = (i & 7) * 16;
            uint32_t so = SW128(r * 128 + c);
            long gi = (long)(row0 + r) * lda + kt + (c >> 1);
            cpasync16(base + so, pAh + gi);
            cpasync16(base + 16384 + so, pAl + gi);
        }
        for (int i = tid; i < BN * 8; i += 256) {
            int r = i >> 3, c = (i & 7) * 16;
            uint32_t so = SW128(r * 128 + c);
            long gi = (long)(col0 + r) * ldb + kt + (c >> 1);
            cpasync16(base + 32768 + so, pBh + gi);
            cpasync16(base + 32768 + BN * 128 + so, pBl + gi);
        }
        CP_COMMIT();
    };

    issue_chunk(0, 0);

    // Fragment double buffers (register-resident; fully unrolled indices)
    uint32_t fah[2][2][4], fal[2][2][4];
    uint32_t fbh[2][NPT][4], fbl[2][NPT][4];

    for (int ch = 0; ch < nch; ch++) {
        const int cur = ch & 1;
        const bool pf = (ch + 1 < nch);
        if (pf) issue_chunk((ch + 1) & 1, ch + 1);
        if (pf) CP_WAIT1(); else CP_WAIT0();
        __syncthreads();

        const uint32_t OAH = sb + OFF0 + cur * STAGE;
        const uint32_t OAL = OAH + 16384;
        const uint32_t OBH = OAH + 32768;
        const uint32_t OBL = OBH + BN * 128;

        // Prime fragments for k16 = 0
#pragma unroll
        for (int mi = 0; mi < 2; mi++) {
            uint32_t off = SW128((wr * 32 + mi * 16 + arow) * 128 + akb);
            ldsm4(OAH + off, fah[0][mi]);
            ldsm4(OAL + off, fal[0][mi]);
        }
#pragma unroll
        for (int np = 0; np < NPT; np++) {
            uint32_t off = SW128((wc * WNT + np * 16 + brow) * 128 + bkb);
            ldsm4(OBH + off, fbh[0][np]);
            ldsm4(OBL + off, fbl[0][np]);
        }

#pragma unroll
        for (int k16 = 0; k16 < 4; k16++) {
            const int cb = k16 & 1;
            const int nb = cb ^ 1;
            if (k16 < 3) {
                // Prefetch next k16's fragments before current MMAs
#pragma unroll
                for (int mi = 0; mi < 2; mi++) {
                    uint32_t off = SW128((wr * 32 + mi * 16 + arow) * 128 +
                                         (k16 + 1) * 32 + akb);
                    ldsm4(OAH + off, fah[nb][mi]);
                    ldsm4(OAL + off, fal[nb][mi]);
                }
#pragma unroll
                for (int np = 0; np < NPT; np++) {
                    uint32_t off = SW128((wc * WNT + np * 16 + brow) * 128 +
                                         (k16 + 1) * 32 + bkb);
                    ldsm4(OBH + off, fbh[nb][np]);
                    ldsm4(OBL + off, fbl[nb][np]);
                }
            }
#pragma unroll
            for (int mi = 0; mi < 2; mi++)
#pragma unroll
                for (int np = 0; np < NPT; np++) {
                    mma16816(acc[mi][2 * np], fah[cb][mi],
                             fbh[cb][np][0], fbh[cb][np][1]);
                    mma16816(acc[mi][2 * np], fah[cb][mi],
                             fbl[cb][np][0], fbl[cb][np][1]);
                    mma16816(acc[mi][2 * np], fal[cb][mi],
                             fbh[cb][np][0], fbh[cb][np][1]);
                    mma16816(acc[mi][2 * np + 1], fah[cb][mi],
                             fbh[cb][np][2], fbh[cb][np][3]);
                    mma16816(acc[mi][2 * np + 1], fah[cb][mi],
                             fbl[cb][np][2], fbl[cb][np][3]);
                    mma16816(acc[mi][2 * np + 1], fal[cb][mi],
                             fbh[cb][np][2], fbh[cb][np][3]);
                }
        }
        __syncthreads();
    }

    // Epilogue: c0=(m=qrow,n=qcol), c1=(m,n+1), c2=(m+8,n), c3=(m+8,n+1)
    const int qrow = lane >> 2;
    const int qcol = (lane & 3) * 2;
#pragma unroll
    for (int mi = 0; mi < 2; mi++) {
        const long rb = row0 + wr * 32 + mi * 16 + qrow;
#pragma unroll
        for (int ni = 0; ni < NI; ni++) {
            const int c = col0 + wc * WNT + ni * 8 + qcol;
            float v0 = acc[mi][ni][0] * alpha;
            float v1 = acc[mi][ni][1] * alpha;
            float v2 = acc[mi][ni][2] * alpha;
            float v3 = acc[mi][ni][3] * alpha;
            if (MODE == 1) {
                v0 += bias[c]; v1 += bias[c + 1];
                v2 += bias[c]; v3 += bias[c + 1];
            }
            if (MODE == 0 || MODE == 1) {
                float* pC = Cf + zq * sC1 + zr * sC2;
                float2 w0; w0.x = v0; w0.y = v1;
                float2 w1; w1.x = v2; w1.y = v3;
                *(float2*)&pC[rb * ldc + c] = w0;
                *(float2*)&pC[(rb + 8) * ldc + c] = w1;
            } else {
                bf16* pH = Ch + zq * sC1 + zr * sC2;
                bf16* pL = Cl + zq * sC1 + zr * sC2;
                bf16 h0, l0, h1, l1, h2, l2, h3, l3;
                split_bf(v0, h0, l0); split_bf(v1, h1, l1);
                split_bf(v2, h2, l2); split_bf(v3, h3, l3);
                bf162 ha; ha.x = h0; ha.y = h1;
                bf162 hb; hb.x = h2; hb.y = h3;
                bf162 la; la.x = l0; la.y = l1;
                bf162 lb; lb.x = l2; lb.y = l3;
                *(bf162*)&pH[rb * ldc + c] = ha;
                *(bf162*)&pL[rb * ldc + c] = la;
                *(bf162*)&pH[(rb + 8) * ldc + c] = hb;
                *(bf162*)&pL[(rb + 8) * ldc + c] = lb;
            }
        }
    }
}

// ---------------------------------------------------------------------------
// Conversion / transpose kernels
// ---------------------------------------------------------------------------
__global__ __launch_bounds__(256)
void splitf_kernel(const float* __restrict__ in, bf16* __restrict__ oh,
                   bf16* __restrict__ ol, int n)
{
    int i = blockIdx.x * 256 + threadIdx.x;
    if (i < n) {
        bf16 h, l;
        split_bf(in[i], h, l);
        oh[i] = h; ol[i] = l;
    }
}

// out[c, r] = split(in[r, c]); in is R x C row-major. Grid (C/32, R/32), blk (32,8)
__global__ __launch_bounds__(256)
void tsplit_kernel(const float* __restrict__ in, bf16* __restrict__ oh,
                   bf16* __restrict__ ol, int R, int C)
{
    __shared__ float t[32][33];
    int c0 = blockIdx.x * 32, r0 = blockIdx.y * 32;
    for (int i = threadIdx.y; i < 32; i += 8)
        t[i][threadIdx.x] = in[(long)(r0 + i) * C + c0 + threadIdx.x];
    __syncthreads();
    for (int i = threadIdx.y; i < 32; i += 8) {
        float v = t[threadIdx.x][i];
        long o = (long)(c0 + i) * R + r0 + threadIdx.x;
        bf16 h, l;
        split_bf(v, h, l);
        oh[o] = h; ol[o] = l;
    }
}

// V^T: g_vt[bh, d, m] = qkv pair [b, m, 1024 + h*64 + d].
__global__ __launch_bounds__(256)
void vtrans_kernel()
{
    __shared__ bf16 th[32][40], tl[32][40];
    const int bh = blockIdx.z;
    const int b = bh >> 3, h = bh & 7;
    const int m0 = blockIdx.x * 32, d0 = blockIdx.y * 32;
    const bf16* ih = g_qkvh + (long)b * KN * KQ + 1024 + h * 64 + d0;
    const bf16* il = g_qkvl + (long)b * KN * KQ + 1024 + h * 64 + d0;
    for (int i = threadIdx.y; i < 32; i += 8) {
        th[i][threadIdx.x] = ih[(long)(m0 + i) * KQ + threadIdx.x];
        tl[i][threadIdx.x] = il[(long)(m0 + i) * KQ + threadIdx.x];
    }
    __syncthreads();
    bf16* oh = g_vth + ((long)bh * KDH + d0) * KN + m0;
    bf16* ol = g_vtl + ((long)bh * KDH + d0) * KN + m0;
    for (int i = threadIdx.y; i < 32; i += 8) {
        oh[(long)i * KN + threadIdx.x] = th[threadIdx.x][i];
        ol[(long)i * KN + threadIdx.x] = tl[threadIdx.x][i];
    }
}

// ---------------------------------------------------------------------------
// Fused per-(b,n): softmax (8 heads) + conv head-mix (-> bf16 pairs) + moments
// ---------------------------------------------------------------------------
__global__ __launch_bounds__(256)
void smconv_kernel(const float* __restrict__ cw)
{
    __shared__ __align__(16) float sa[KH][KN];
    __shared__ float sinv[KH];
    __shared__ float scw[64];
    __shared__ float red[8][36];

    const int bidx = blockIdx.x;
    const int b = bidx >> 10;
    const int n = bidx & (KN - 1);
    const long hs = (long)KN * KN;
    const float* base = g_attn + (long)b * KH * hs + (long)n * KN;
    bf16* chb = g_ch + (long)b * KH * hs + (long)n * KN;
    bf16* clb = g_cl + (long)b * KH * hs + (long)n * KN;

    const int tid = threadIdx.x;

    for (int i = tid; i < KH * KN / 4; i += 256) {
        int h = i >> 8;
        int m4 = (i & 255) * 4;
        *reinterpret_cast<float4*>(&sa[h][m4]) =
            *reinterpret_cast<const float4*>(&base[(long)h * hs + m4]);
    }
    __syncthreads();

    {
        const int w = tid >> 5, lane = tid & 31;
        float vmax = -1e30f;
        for (int i = lane; i < KN; i += 32) vmax = fmaxf(vmax, sa[w][i]);
#pragma unroll
        for (int o = 16; o; o >>= 1)
            vmax = fmaxf(vmax, __shfl_xor_sync(0xffffffffu, vmax, o));
        float s = 0.f;
        for (int i = lane; i < KN; i += 32) {
            float e = __expf(sa[w][i] - vmax);
            sa[w][i] = e;
            s += e;
        }
#pragma unroll
        for (int o = 16; o; o >>= 1) s += __shfl_xor_sync(0xffffffffu, s, o);
        if (lane == 0) sinv[w] = 1.0f / s;
    }
    __syncthreads();
    if (tid < 64) scw[tid] = cw[tid] * sinv[tid & 7];
    __syncthreads();

    const int m0 = tid * 4;
    float4 av[KH];
#pragma unroll
    for (int h = 0; h < KH; h++)
        av[h] = *reinterpret_cast<const float4*>(&sa[h][m0]);

    float s36[36];
#pragma unroll
    for (int p = 0; p < 36; p++) s36[p] = 0.f;
    float cv[KH][4];

#pragma unroll
    for (int e = 0; e < 4; e++) {
        float a8[KH];
#pragma unroll
        for (int h = 0; h < KH; h++)
            a8[h] = (e == 0) ? av[h].x : (e == 1) ? av[h].y
                   : (e == 2) ? av[h].z : av[h].w;
        int p = 0;
#pragma unroll
        for (int h = 0; h < KH; h++)
#pragma unroll
            for (int h2 = h; h2 < KH; h2++) s36[p++] += a8[h] * a8[h2];
#pragma unroll
        for (int g = 0; g < KH; g++) {
            float c = 0.f;
#pragma unroll
            for (int h = 0; h < KH; h++) c += scw[g * 8 + h] * a8[h];
            cv[g][e] = c;
        }
    }
#pragma unroll
    for (int g = 0; g < KH; g++) {
        bf16 h0, l0, h1, l1, h2, l2, h3, l3;
        split_bf(cv[g][0], h0, l0);
        split_bf(cv[g][1], h1, l1);
        split_bf(cv[g][2], h2, l2);
        split_bf(cv[g][3], h3, l3);
        bf162 ha; ha.x = h0; ha.y = h1;
        bf162 hb; hb.x = h2; hb.y = h3;
        bf162 la; la.x = l0; la.y = l1;
        bf162 lb; lb.x = l2; lb.y = l3;
        *(bf162*)&chb[(long)g * hs + m0]     = ha;
        *(bf162*)&chb[(long)g * hs + m0 + 2] = hb;
        *(bf162*)&clb[(long)g * hs + m0]     = la;
        *(bf162*)&clb[(long)g * hs + m0 + 2] = lb;
    }

    const int lane = tid & 31, warp = tid >> 5;
#pragma unroll
    for (int p = 0; p < 36; p++) {
        float v = s36[p];
#pragma unroll
        for (int o = 16; o; o >>= 1) v += __shfl_xor_sync(0xffffffffu, v, o);
        if (lane == 0) red[warp][p] = v;
    }
    __syncthreads();
    if (tid < 36) {
        float v = 0.f;
#pragma unroll
        for (int w = 0; w < 8; w++) v += red[w][tid];
        int h = 0, rem = tid;
        while (rem >= KH - h) { rem -= KH - h; h++; }
        int h2 = h + rem;
        g_part[(long)bidx * 36 + tid] = v * sinv[h] * sinv[h2];
    }
}

// Deterministic reduction of moment partials -> g_S (means).
__global__ __launch_bounds__(256)
void reduce_kernel()
{
    const int p = blockIdx.x;
    float v = 0.f;
    for (int i = threadIdx.x; i < KB * KN; i += 256)
        v += g_part[(long)i * 36 + p];
    __shared__ float sm[256];
    sm[threadIdx.x] = v;
    __syncthreads();
    for (int o = 128; o; o >>= 1) {
        if (threadIdx.x < o) sm[threadIdx.x] += sm[threadIdx.x + o];
        __syncthreads();
    }
    if (threadIdx.x == 0) g_S[p] = sm[0] * (1.0f / 8388608.0f);
}

// Vsum[b,h,d] = sum_m V[b,h,m,d] (from bf16 pairs).
__global__ __launch_bounds__(256)
void vsum_kernel()
{
    const int bh = blockIdx.x;
    const int t = threadIdx.x;
    const int d = t & 63;
    const int q = t >> 6;
    const int b = bh >> 3, h = bh & 7;
    const bf16* ph = g_qkvh + (long)b * KN * KQ + 1024 + h * 64 + d;
    const bf16* pl = g_qkvl + (long)b * KN * KQ + 1024 + h * 64 + d;
    float s = 0.f;
    for (int m = q * 256; m < (q + 1) * 256; m++)
        s += __bfloat162float(ph[(long)m * KQ]) + __bfloat162float(pl[(long)m * KQ]);
    __shared__ float sm[256];
    sm[t] = s;
    __syncthreads();
    if (q == 0)
        g_vsum[bh * 64 + d] = sm[d] + sm[64 + d] + sm[128 + d] + sm[192 + d];
}

// BatchNorm coefficients from analytic mean + cross moments.
__global__ void stats_kernel(const float* __restrict__ cw,
                             const float* __restrict__ cb,
                             const float* __restrict__ gamma,
                             const float* __restrict__ beta)
{
    int g = threadIdx.x;
    if (g >= KH) return;
    float Sf[8][8];
    int p = 0;
    for (int h = 0; h < 8; h++)
        for (int h2 = h; h2 < 8; h2++) {
            float v = g_S[p++];
            Sf[h][h2] = v; Sf[h2][h] = v;
        }
    float meanC = 0.f;
    for (int h = 0; h < 8; h++) meanC += cw[g * 8 + h];
    meanC *= (1.0f / KN);
    float mean = meanC + cb[g];
    float e2 = cb[g] * cb[g] + 2.f * cb[g] * meanC;
    for (int h = 0; h < 8; h++)
        for (int h2 = 0; h2 < 8; h2++)
            e2 += cw[g * 8 + h] * cw[g * 8 + h2] * Sf[h][h2];
    float var = e2 - mean * mean;
    float s = gamma[g] * rsqrtf(var + 1e-5f);
    g_k1[g] = s;
    g_k0[g] = beta[g] - s * meanC;
}

// Y[b,n,h*64+d] = k1[h]*U[b,h,n,d] + k0[h]*Vsum[b,h,d], split to bf16 pair
__global__ __launch_bounds__(256)
void assemble_kernel()
{
    int i = blockIdx.x * 256 + threadIdx.x;
    int c = i & 511;
    int h = c >> 6;
    int d = c & 63;
    int bn = i >> 9;
    int n = bn & (KN - 1);
    int b = bn >> 10;
    long ui = ((((long)b * KH + h) * KN) + n) * KDH + d;
    float v = g_k1[h] * g_u[ui] + g_k0[h] * g_vsum[(b * KH + h) * KDH + d];
    bf16 hh, ll;
    split_bf(v, hh, ll);
    g_yh[i] = hh; g_yl[i] = ll;
}

// ---------------------------------------------------------------------------
// Launch
// ---------------------------------------------------------------------------
extern "C" void kernel_launch(void* const* d_in, const int* in_sizes, int n_in,
                              void* d_out, int out_size)
{
    const float* x      = (const float*)d_in[0];
    const float* w_qkv  = (const float*)d_in[1];
    const float* conv_w = (const float*)d_in[2];
    const float* conv_b = (const float*)d_in[3];
    const float* gamma  = (const float*)d_in[4];
    const float* beta   = (const float*)d_in[5];
    const float* w_out  = (const float*)d_in[6];
    const float* b_out  = (const float*)d_in[7];
    float* out = (float*)d_out;

    constexpr int SMEM128 = 1024 + 2 * (32768 + 128 * 256);   // 132096
    constexpr int SMEM64  = 1024 + 2 * (32768 + 64 * 256);    //  99328
    cudaFuncSetAttribute(tc_gemm<128, 0>,
        cudaFuncAttributeMaxDynamicSharedMemorySize, SMEM128);
    cudaFuncSetAttribute(tc_gemm<128, 1>,
        cudaFuncAttributeMaxDynamicSharedMemorySize, SMEM128);
    cudaFuncSetAttribute(tc_gemm<128, 2>,
        cudaFuncAttributeMaxDynamicSharedMemorySize, SMEM128);
    cudaFuncSetAttribute(tc_gemm<64, 0>,
        cudaFuncAttributeMaxDynamicSharedMemorySize, SMEM64);

    void *p_xh, *p_xl, *p_wqh, *p_wql, *p_woh, *p_wol;
    void *p_qh, *p_ql, *p_attn, *p_ch, *p_cl, *p_vth, *p_vtl;
    void *p_u, *p_yh, *p_yl;
    cudaGetSymbolAddress(&p_xh,  g_xh);  cudaGetSymbolAddress(&p_xl,  g_xl);
    cudaGetSymbolAddress(&p_wqh, g_wqh); cudaGetSymbolAddress(&p_wql, g_wql);
    cudaGetSymbolAddress(&p_woh, g_woh); cudaGetSymbolAddress(&p_wol, g_wol);
    cudaGetSymbolAddress(&p_qh,  g_qkvh); cudaGetSymbolAddress(&p_ql, g_qkvl);
    cudaGetSymbolAddress(&p_attn, g_attn);
    cudaGetSymbolAddress(&p_ch,  g_ch);  cudaGetSymbolAddress(&p_cl,  g_cl);
    cudaGetSymbolAddress(&p_vth, g_vth); cudaGetSymbolAddress(&p_vtl, g_vtl);
    cudaGetSymbolAddress(&p_u,   g_u);
    cudaGetSymbolAddress(&p_yh,  g_yh);  cudaGetSymbolAddress(&p_yl,  g_yl);

    // 0) Operand conversions
    splitf_kernel<<<(KB * KN * KD) / 256, 256>>>(x, (bf16*)p_xh, (bf16*)p_xl,
                                                 KB * KN * KD);
    tsplit_kernel<<<dim3(KQ / 32, KD / 32), dim3(32, 8)>>>(
        w_qkv, (bf16*)p_wqh, (bf16*)p_wql, KD, KQ);
    tsplit_kernel<<<dim3(KD / 32, KD / 32), dim3(32, 8)>>>(
        w_out, (bf16*)p_woh, (bf16*)p_wol, KD, KD);

    // 1) QKV: [8192,1536] = x @ w_qkv  -> bf16 pair output
    tc_gemm<128, 2><<<dim3(KQ / 128, (KB * KN) / 128, 1), 256, SMEM128>>>(
        (const bf16*)p_xh, (const bf16*)p_xl,
        (const bf16*)p_wqh, (const bf16*)p_wql,
        nullptr, (bf16*)p_qh, (bf16*)p_ql, nullptr,
        KD, KD, KD, KQ,
        1, 0, 0, 0, 0, 0, 0, 1.0f);

    // 2) Logits per (b,h): A = 0.125 * Q @ K^T -> fp32
    tc_gemm<128, 0><<<dim3(KN / 128, KN / 128, KB * KH), 256, SMEM128>>>(
        (const bf16*)p_qh, (const bf16*)p_ql,
        (const bf16*)p_qh + 512, (const bf16*)p_ql + 512,
        (float*)p_attn, nullptr, nullptr, nullptr,
        KDH, KQ, KQ, KN,
        KH, (long)KN * KQ, 64, (long)KN * KQ, 64,
        (long)KH * KN * KN, (long)KN * KN, 0.125f);

    // 3) Fused softmax + conv head-mix (bf16 pair out) + cross moments
    smconv_kernel<<<KB * KN, 256>>>(conv_w);

    // 4) Stats path + V^T
    reduce_kernel<<<36, 256>>>();
    vsum_kernel<<<KB * KH, 256>>>();
    stats_kernel<<<1, 32>>>(conv_w, conv_b, gamma, beta);
    vtrans_kernel<<<dim3(KN / 32, KDH / 32, KB * KH), dim3(32, 8)>>>();

    // 5) U[b,h] = C[b,h] @ V[b,h]  (M=1024, N=64, K=1024) -> fp32
    tc_gemm<64, 0><<<dim3(1, KN / 128, KB * KH), 256, SMEM64>>>(
        (const bf16*)p_ch, (const bf16*)p_cl,
        (const bf16*)p_vth, (const bf16*)p_vtl,
        (float*)p_u, nullptr, nullptr, nullptr,
        KN, KN, KN, KDH,
        KH, (long)KH * KN * KN, (long)KN * KN,
        (long)KH * KDH * KN, (long)KDH * KN,
        (long)KH * KN * KDH, (long)KN * KDH, 1.0f);

    // 6) Assemble Y (deferred BN affine) -> bf16 pair
    assemble_kernel<<<(KB * KN * KD) / 256, 256>>>();

    // 7) out = Y @ w_out + b_out
    tc_gemm<128, 1><<<dim3(KD / 128, (KB * KN) / 128, 1), 256, SMEM128>>>(
        (const bf16*)p_yh, (const bf16*)p_yl,
        (const bf16*)p_woh, (const bf16*)p_wol,
        out, nullptr, nullptr, b_out,
        KD, KD, KD, KD,
        1, 0, 0, 0, 0, 0, 0, 1.0f);
}

// round 12
// speedup vs baseline: 1.0563x; 1.0563x over previous
#include <cuda_runtime.h>
#include <cuda_bf16.h>
#include <math.h>
#include <cstdint>

// Problem constants
#define KB   8      // batch
#define KN   1024   // sequence length
#define KD   512    // model dim
#define KH   8      // heads
#define KDH  64     // dim per head
#define KQ   1536   // qkv columns

typedef __nv_bfloat16 bf16;
typedef __nv_bfloat162 bf162;

// ---------------------------------------------------------------------------
// Scratch (static __device__ arrays; allocation-free per harness rules)
// ---------------------------------------------------------------------------
__device__ __align__(16) bf16  g_xh [KB * KN * KD];           // x split hi
__device__ __align__(16) bf16  g_xl [KB * KN * KD];           // x split lo
__device__ __align__(16) bf16  g_wqh[KQ * KD];                // w_qkv^T hi
__device__ __align__(16) bf16  g_wql[KQ * KD];
__device__ __align__(16) bf16  g_woh[KD * KD];                // w_out^T hi
__device__ __align__(16) bf16  g_wol[KD * KD];
__device__ __align__(16) bf16  g_qkvh[KB * KN * KQ];          // qkv split hi
__device__ __align__(16) bf16  g_qkvl[KB * KN * KQ];
__device__ __align__(16) float g_attn[KB * KH * KN * KN];     // raw logits (fp32)
__device__ __align__(16) bf16  g_ch [KB * KH * KN * KN];      // C = conv-mix, hi
__device__ __align__(16) bf16  g_cl [KB * KH * KN * KN];      // C lo
__device__ __align__(16) bf16  g_vth[KB * KH * KDH * KN];     // V^T [bh, d, m] hi
__device__ __align__(16) bf16  g_vtl[KB * KH * KDH * KN];
__device__ __align__(16) float g_u  [KB * KH * KN * KDH];     // U = C @ V (fp32)
__device__ __align__(16) bf16  g_yh [KB * KN * KD];           // Y split hi
__device__ __align__(16) bf16  g_yl [KB * KN * KD];
__device__ __align__(16) float g_vsum[KB * KH * KDH];
__device__ __align__(16) float g_part[KB * KN * 36];
__device__ __align__(16) float g_S  [36];
__device__ float g_k0[KH];
__device__ float g_k1[KH];

// ---------------------------------------------------------------------------
// Helpers
// ---------------------------------------------------------------------------
__device__ __forceinline__ uint32_t smem_u32(const void* p) {
    uint32_t a;
    asm("{ .reg .u64 t; cvta.to.shared.u64 t, %1; cvt.u32.u64 %0, t; }"
        : "=r"(a) : "l"(p));
    return a;
}
#define SW128(x) ((x) ^ (((x) >> 3) & 0x70))

__device__ __forceinline__ void split_bf(float v, bf16& h, bf16& l) {
    h = __float2bfloat16(v);
    l = __float2bfloat16(v - __bfloat162float(h));
}

// ldmatrix x4 (b16)
__device__ __forceinline__ void ldsm4(uint32_t addr, uint32_t* r) {
    asm volatile("ldmatrix.sync.aligned.m8n8.x4.shared.b16 {%0,%1,%2,%3}, [%4];"
                 : "=r"(r[0]), "=r"(r[1]), "=r"(r[2]), "=r"(r[3]) : "r"(addr));
}
// mma m16n8k16 bf16 -> f32 accumulate
__device__ __forceinline__ void mma16816(float* c, const uint32_t* a,
                                         uint32_t b0, uint32_t b1) {
    asm volatile(
        "mma.sync.aligned.m16n8k16.row.col.f32.bf16.bf16.f32 "
        "{%0,%1,%2,%3}, {%4,%5,%6,%7}, {%8,%9}, {%0,%1,%2,%3};"
        : "+f"(c[0]), "+f"(c[1]), "+f"(c[2]), "+f"(c[3])
        : "r"(a[0]), "r"(a[1]), "r"(a[2]), "r"(a[3]), "r"(b0), "r"(b1));
}
// 16-byte async copy global -> shared
__device__ __forceinline__ void cpasync16(uint32_t s, const void* g) {
    asm volatile("cp.async.cg.shared.global [%0], [%1], 16;"
                 :: "r"(s), "l"(g));
}
#define CP_COMMIT()  asm volatile("cp.async.commit_group;" ::: "memory")
#define CP_WAIT0()   asm volatile("cp.async.wait_group 0;" ::: "memory")
#define CP_WAIT1()   asm volatile("cp.async.wait_group 1;" ::: "memory")

// ---------------------------------------------------------------------------
// bf16x2-split GEMM, BM=128 x BN=64 tile, 2-stage cp.async pipeline,
// 2 CTAs/SM (regs capped at 128 via launch_bounds).
//   D[128 x 64] = alpha * A @ B^T (+bias)
//   A rows K-major (bf16 hi/lo), B rows K-major (B[n][k]). K multiple of 64.
//   MODE 0: fp32 out *alpha; 1: fp32 *alpha + bias; 2: bf16 hi/lo pair out.
// ---------------------------------------------------------------------------
template <int MODE>
__global__ __launch_bounds__(256, 2)
void tc_gemm(const bf16* __restrict__ Ah, const bf16* __restrict__ Al,
             const bf16* __restrict__ Bh, const bf16* __restrict__ Bl,
             float* __restrict__ Cf, bf16* __restrict__ Ch,
             bf16* __restrict__ Cl, const float* __restrict__ bias,
             int K, int lda, int ldb, int ldc,
             int HB, long sA1, long sA2, long sB1, long sB2,
             long sC1, long sC2, float alpha)
{
    constexpr int BN = 64;
    extern __shared__ __align__(1024) char smem[];
    constexpr int STAGE = 32768 + BN * 256;   // AH(16K)+AL(16K)+BH(8K)+BL(8K)
    constexpr int OFF0  = 1024;

    const uint32_t sb = smem_u32(smem);
    const int tid = threadIdx.x, wid = tid >> 5, lane = tid & 31;
    const int z = blockIdx.z;
    const long zq = z / HB, zr = z % HB;
    const bf16* pAh = Ah + zq * sA1 + zr * sA2;
    const bf16* pAl = Al + zq * sA1 + zr * sA2;
    const bf16* pBh = Bh + zq * sB1 + zr * sB2;
    const bf16* pBl = Bl + zq * sB1 + zr * sB2;
    const int row0 = blockIdx.y * 128;
    const int col0 = blockIdx.x * BN;
    const int nch = K >> 6;

    constexpr int WNT = 32;              // warp n-tile width
    constexpr int NI  = 4;               // n 16x8 tiles per warp
    constexpr int NPT = 2;               // ldmatrix.x4 pairs per warp
    const int wr = wid & 3;              // row group (32 rows)
    const int wc = wid >> 2;             // col group (2 groups x 32 cols)

    float acc[2][NI][4];
#pragma unroll
    for (int mi = 0; mi < 2; mi++)
#pragma unroll
        for (int ni = 0; ni < NI; ni++)
#pragma unroll
            for (int e = 0; e < 4; e++) acc[mi][ni][e] = 0.f;

    const int arow = lane & 15;
    const int akb  = (lane >> 4) << 4;
    const int brow = ((lane >> 4) << 3) + (lane & 7);
    const int bkb  = ((lane >> 3) & 1) << 4;

    // --- async stage loader: chunk ch -> stage st ---
    auto issue_chunk = [&](int st, int ch) {
        const int kt = ch << 6;
        const uint32_t base = sb + OFF0 + st * STAGE;
        for (int i = tid; i < 128 * 8; i += 256) {
            int r = i >> 3, c = (i & 7) * 16;
            uint32_t so = SW128(r * 128 + c);
            long gi = (long)(row0 + r) * lda + kt + (c >> 1);
            cpasync16(base + so, pAh + gi);
            cpasync16(base + 16384 + so, pAl + gi);
        }
        for (int i = tid; i < BN * 8; i += 256) {
            int r = i >> 3, c = (i & 7) * 16;
            uint32_t so = SW128(r * 128 + c);
            long gi = (long)(col0 + r) * ldb + kt + (c >> 1);
            cpasync16(base + 32768 + so, pBh + gi);
            cpasync16(base + 32768 + BN * 128 + so, pBl + gi);
        }
        CP_COMMIT();
    };

    issue_chunk(0, 0);

    for (int ch = 0; ch < nch; ch++) {
        const int cur = ch & 1;
        const bool pf = (ch + 1 < nch);
        if (pf) issue_chunk((ch + 1) & 1, ch + 1);
        if (pf) CP_WAIT1(); else CP_WAIT0();
        __syncthreads();

        const uint32_t OAH = sb + OFF0 + cur * STAGE;
        const uint32_t OAL = OAH + 16384;
        const uint32_t OBH = OAH + 32768;
        const uint32_t OBL = OBH + BN * 128;

#pragma unroll
        for (int k16 = 0; k16 < 4; k16++) {
            uint32_t ah[2][4], al2[2][4];
#pragma unroll
            for (int mi = 0; mi < 2; mi++) {
                uint32_t off = SW128((wr * 32 + mi * 16 + arow) * 128 +
                                     k16 * 32 + akb);
                ldsm4(OAH + off, ah[mi]);
                ldsm4(OAL + off, al2[mi]);
            }
            uint32_t bh2[NPT][4], bl2[NPT][4];
#pragma unroll
            for (int np = 0; np < NPT; np++) {
                uint32_t off = SW128((wc * WNT + np * 16 + brow) * 128 +
                                     k16 * 32 + bkb);
                ldsm4(OBH + off, bh2[np]);
                ldsm4(OBL + off, bl2[np]);
            }
#pragma unroll
            for (int mi = 0; mi < 2; mi++)
#pragma unroll
                for (int np = 0; np < NPT; np++) {
                    mma16816(acc[mi][2 * np], ah[mi], bh2[np][0], bh2[np][1]);
                    mma16816(acc[mi][2 * np], ah[mi], bl2[np][0], bl2[np][1]);
                    mma16816(acc[mi][2 * np], al2[mi], bh2[np][0], bh2[np][1]);
                    mma16816(acc[mi][2 * np + 1], ah[mi], bh2[np][2], bh2[np][3]);
                    mma16816(acc[mi][2 * np + 1], ah[mi], bl2[np][2], bl2[np][3]);
                    mma16816(acc[mi][2 * np + 1], al2[mi], bh2[np][2], bh2[np][3]);
                }
        }
        __syncthreads();
    }

    // Epilogue: c0=(m=qrow,n=qcol), c1=(m,n+1), c2=(m+8,n), c3=(m+8,n+1)
    const int qrow = lane >> 2;
    const int qcol = (lane & 3) * 2;
#pragma unroll
    for (int mi = 0; mi < 2; mi++) {
        const long rb = row0 + wr * 32 + mi * 16 + qrow;
#pragma unroll
        for (int ni = 0; ni < NI; ni++) {
            const int c = col0 + wc * WNT + ni * 8 + qcol;
            float v0 = acc[mi][ni][0] * alpha;
            float v1 = acc[mi][ni][1] * alpha;
            float v2 = acc[mi][ni][2] * alpha;
            float v3 = acc[mi][ni][3] * alpha;
            if (MODE == 1) {
                v0 += bias[c]; v1 += bias[c + 1];
                v2 += bias[c]; v3 += bias[c + 1];
            }
            if (MODE == 0 || MODE == 1) {
                float* pC = Cf + zq * sC1 + zr * sC2;
                float2 w0; w0.x = v0; w0.y = v1;
                float2 w1; w1.x = v2; w1.y = v3;
                *(float2*)&pC[rb * ldc + c] = w0;
                *(float2*)&pC[(rb + 8) * ldc + c] = w1;
            } else {
                bf16* pH = Ch + zq * sC1 + zr * sC2;
                bf16* pL = Cl + zq * sC1 + zr * sC2;
                bf16 h0, l0, h1, l1, h2, l2, h3, l3;
                split_bf(v0, h0, l0); split_bf(v1, h1, l1);
                split_bf(v2, h2, l2); split_bf(v3, h3, l3);
                bf162 ha; ha.x = h0; ha.y = h1;
                bf162 hb; hb.x = h2; hb.y = h3;
                bf162 la; la.x = l0; la.y = l1;
                bf162 lb; lb.x = l2; lb.y = l3;
                *(bf162*)&pH[rb * ldc + c] = ha;
                *(bf162*)&pL[rb * ldc + c] = la;
                *(bf162*)&pH[(rb + 8) * ldc + c] = hb;
                *(bf162*)&pL[(rb + 8) * ldc + c] = lb;
            }
        }
    }
}

// ---------------------------------------------------------------------------
// Conversion / transpose kernels
// ---------------------------------------------------------------------------
__global__ __launch_bounds__(256)
void splitf_kernel(const float* __restrict__ in, bf16* __restrict__ oh,
                   bf16* __restrict__ ol, int n)
{
    int i = blockIdx.x * 256 + threadIdx.x;
    if (i < n) {
        bf16 h, l;
        split_bf(in[i], h, l);
        oh[i] = h; ol[i] = l;
    }
}

// out[c, r] = split(in[r, c]); in is R x C row-major. Grid (C/32, R/32), blk (32,8)
__global__ __launch_bounds__(256)
void tsplit_kernel(const float* __restrict__ in, bf16* __restrict__ oh,
                   bf16* __restrict__ ol, int R, int C)
{
    __shared__ float t[32][33];
    int c0 = blockIdx.x * 32, r0 = blockIdx.y * 32;
    for (int i = threadIdx.y; i < 32; i += 8)
        t[i][threadIdx.x] = in[(long)(r0 + i) * C + c0 + threadIdx.x];
    __syncthreads();
    for (int i = threadIdx.y; i < 32; i += 8) {
        float v = t[threadIdx.x][i];
        long o = (long)(c0 + i) * R + r0 + threadIdx.x;
        bf16 h, l;
        split_bf(v, h, l);
        oh[o] = h; ol[o] = l;
    }
}

// V^T: g_vt[bh, d, m] = qkv pair [b, m, 1024 + h*64 + d].
__global__ __launch_bounds__(256)
void vtrans_kernel()
{
    __shared__ bf16 th[32][40], tl[32][40];
    const int bh = blockIdx.z;
    const int b = bh >> 3, h = bh & 7;
    const int m0 = blockIdx.x * 32, d0 = blockIdx.y * 32;
    const bf16* ih = g_qkvh + (long)b * KN * KQ + 1024 + h * 64 + d0;
    const bf16* il = g_qkvl + (long)b * KN * KQ + 1024 + h * 64 + d0;
    for (int i = threadIdx.y; i < 32; i += 8) {
        th[i][threadIdx.x] = ih[(long)(m0 + i) * KQ + threadIdx.x];
        tl[i][threadIdx.x] = il[(long)(m0 + i) * KQ + threadIdx.x];
    }
    __syncthreads();
    bf16* oh = g_vth + ((long)bh * KDH + d0) * KN + m0;
    bf16* ol = g_vtl + ((long)bh * KDH + d0) * KN + m0;
    for (int i = threadIdx.y; i < 32; i += 8) {
        oh[(long)i * KN + threadIdx.x] = th[threadIdx.x][i];
        ol[(long)i * KN + threadIdx.x] = tl[threadIdx.x][i];
    }
}

// ---------------------------------------------------------------------------
// Fused per-(b,n): softmax (8 heads) + conv head-mix (-> bf16 pairs) + moments
// ---------------------------------------------------------------------------
__global__ __launch_bounds__(256)
void smconv_kernel(const float* __restrict__ cw)
{
    __shared__ __align__(16) float sa[KH][KN];
    __shared__ float sinv[KH];
    __shared__ float scw[64];
    __shared__ float red[8][36];

    const int bidx = blockIdx.x;
    const int b = bidx >> 10;
    const int n = bidx & (KN - 1);
    const long hs = (long)KN * KN;
    const float* base = g_attn + (long)b * KH * hs + (long)n * KN;
    bf16* chb = g_ch + (long)b * KH * hs + (long)n * KN;
    bf16* clb = g_cl + (long)b * KH * hs + (long)n * KN;

    const int tid = threadIdx.x;

    for (int i = tid; i < KH * KN / 4; i += 256) {
        int h = i >> 8;
        int m4 = (i & 255) * 4;
        *reinterpret_cast<float4*>(&sa[h][m4]) =
            *reinterpret_cast<const float4*>(&base[(long)h * hs + m4]);
    }
    __syncthreads();

    {
        const int w = tid >> 5, lane = tid & 31;
        float vmax = -1e30f;
        for (int i = lane; i < KN; i += 32) vmax = fmaxf(vmax, sa[w][i]);
#pragma unroll
        for (int o = 16; o; o >>= 1)
            vmax = fmaxf(vmax, __shfl_xor_sync(0xffffffffu, vmax, o));
        float s = 0.f;
        for (int i = lane; i < KN; i += 32) {
            float e = __expf(sa[w][i] - vmax);
            sa[w][i] = e;
            s += e;
        }
#pragma unroll
        for (int o = 16; o; o >>= 1) s += __shfl_xor_sync(0xffffffffu, s, o);
        if (lane == 0) sinv[w] = 1.0f / s;
    }
    __syncthreads();
    if (tid < 64) scw[tid] = cw[tid] * sinv[tid & 7];
    __syncthreads();

    const int m0 = tid * 4;
    float4 av[KH];
#pragma unroll
    for (int h = 0; h < KH; h++)
        av[h] = *reinterpret_cast<const float4*>(&sa[h][m0]);

    float s36[36];
#pragma unroll
    for (int p = 0; p < 36; p++) s36[p] = 0.f;
    float cv[KH][4];

#pragma unroll
    for (int e = 0; e < 4; e++) {
        float a8[KH];
#pragma unroll
        for (int h = 0; h < KH; h++)
            a8[h] = (e == 0) ? av[h].x : (e == 1) ? av[h].y
                   : (e == 2) ? av[h].z : av[h].w;
        int p = 0;
#pragma unroll
        for (int h = 0; h < KH; h++)
#pragma unroll
            for (int h2 = h; h2 < KH; h2++) s36[p++] += a8[h] * a8[h2];
#pragma unroll
        for (int g = 0; g < KH; g++) {
            float c = 0.f;
#pragma unroll
            for (int h = 0; h < KH; h++) c += scw[g * 8 + h] * a8[h];
            cv[g][e] = c;
        }
    }
#pragma unroll
    for (int g = 0; g < KH; g++) {
        bf16 h0, l0, h1, l1, h2, l2, h3, l3;
        split_bf(cv[g][0], h0, l0);
        split_bf(cv[g][1], h1, l1);
        split_bf(cv[g][2], h2, l2);
        split_bf(cv[g][3], h3, l3);
        bf162 ha; ha.x = h0; ha.y = h1;
        bf162 hb; hb.x = h2; hb.y = h3;
        bf162 la; la.x = l0; la.y = l1;
        bf162 lb; lb.x = l2; lb.y = l3;
        *(bf162*)&chb[(long)g * hs + m0]     = ha;
        *(bf162*)&chb[(long)g * hs + m0 + 2] = hb;
        *(bf162*)&clb[(long)g * hs + m0]     = la;
        *(bf162*)&clb[(long)g * hs + m0 + 2] = lb;
    }

    const int lane = tid & 31, warp = tid >> 5;
#pragma unroll
    for (int p = 0; p < 36; p++) {
        float v = s36[p];
#pragma unroll
        for (int o = 16; o; o >>= 1) v += __shfl_xor_sync(0xffffffffu, v, o);
        if (lane == 0) red[warp][p] = v;
    }
    __syncthreads();
    if (tid < 36) {
        float v = 0.f;
#pragma unroll
        for (int w = 0; w < 8; w++) v += red[w][tid];
        int h = 0, rem = tid;
        while (rem >= KH - h) { rem -= KH - h; h++; }
        int h2 = h + rem;
        g_part[(long)bidx * 36 + tid] = v * sinv[h] * sinv[h2];
    }
}

// Deterministic reduction of moment partials -> g_S (means).
__global__ __launch_bounds__(256)
void reduce_kernel()
{
    const int p = blockIdx.x;
    float v = 0.f;
    for (int i = threadIdx.x; i < KB * KN; i += 256)
        v += g_part[(long)i * 36 + p];
    __shared__ float sm[256];
    sm[threadIdx.x] = v;
    __syncthreads();
    for (int o = 128; o; o >>= 1) {
        if (threadIdx.x < o) sm[threadIdx.x] += sm[threadIdx.x + o];
        __syncthreads();
    }
    if (threadIdx.x == 0) g_S[p] = sm[0] * (1.0f / 8388608.0f);
}

// Vsum[b,h,d] = sum_m V[b,h,m,d] (from bf16 pairs).
__global__ __launch_bounds__(256)
void vsum_kernel()
{
    const int bh = blockIdx.x;
    const int t = threadIdx.x;
    const int d = t & 63;
    const int q = t >> 6;
    const int b = bh >> 3, h = bh & 7;
    const bf16* ph = g_qkvh + (long)b * KN * KQ + 1024 + h * 64 + d;
    const bf16* pl = g_qkvl + (long)b * KN * KQ + 1024 + h * 64 + d;
    float s = 0.f;
    for (int m = q * 256; m < (q + 1) * 256; m++)
        s += __bfloat162float(ph[(long)m * KQ]) + __bfloat162float(pl[(long)m * KQ]);
    __shared__ float sm[256];
    sm[t] = s;
    __syncthreads();
    if (q == 0)
        g_vsum[bh * 64 + d] = sm[d] + sm[64 + d] + sm[128 + d] + sm[192 + d];
}

// BatchNorm coefficients from analytic mean + cross moments.
__global__ void stats_kernel(const float* __restrict__ cw,
                             const float* __restrict__ cb,
                             const float* __restrict__ gamma,
                             const float* __restrict__ beta)
{
    int g = threadIdx.x;
    if (g >= KH) return;
    float Sf[8][8];
    int p = 0;
    for (int h = 0; h < 8; h++)
        for (int h2 = h; h2 < 8; h2++) {
            float v = g_S[p++];
            Sf[h][h2] = v; Sf[h2][h] = v;
        }
    float meanC = 0.f;
    for (int h = 0; h < 8; h++) meanC += cw[g * 8 + h];
    meanC *= (1.0f / KN);
    float mean = meanC + cb[g];
    float e2 = cb[g] * cb[g] + 2.f * cb[g] * meanC;
    for (int h = 0; h < 8; h++)
        for (int h2 = 0; h2 < 8; h2++)
            e2 += cw[g * 8 + h] * cw[g * 8 + h2] * Sf[h][h2];
    float var = e2 - mean * mean;
    float s = gamma[g] * rsqrtf(var + 1e-5f);
    g_k1[g] = s;
    g_k0[g] = beta[g] - s * meanC;
}

// Y[b,n,h*64+d] = k1[h]*U[b,h,n,d] + k0[h]*Vsum[b,h,d], split to bf16 pair
__global__ __launch_bounds__(256)
void assemble_kernel()
{
    int i = blockIdx.x * 256 + threadIdx.x;
    int c = i & 511;
    int h = c >> 6;
    int d = c & 63;
    int bn = i >> 9;
    int n = bn & (KN - 1);
    int b = bn >> 10;
    long ui = ((((long)b * KH + h) * KN) + n) * KDH + d;
    float v = g_k1[h] * g_u[ui] + g_k0[h] * g_vsum[(b * KH + h) * KDH + d];
    bf16 hh, ll;
    split_bf(v, hh, ll);
    g_yh[i] = hh; g_yl[i] = ll;
}

// ---------------------------------------------------------------------------
// Launch
// ---------------------------------------------------------------------------
extern "C" void kernel_launch(void* const* d_in, const int* in_sizes, int n_in,
                              void* d_out, int out_size)
{
    const float* x      = (const float*)d_in[0];
    const float* w_qkv  = (const float*)d_in[1];
    const float* conv_w = (const float*)d_in[2];
    const float* conv_b = (const float*)d_in[3];
    const float* gamma  = (const float*)d_in[4];
    const float* beta   = (const float*)d_in[5];
    const float* w_out  = (const float*)d_in[6];
    const float* b_out  = (const float*)d_in[7];
    float* out = (float*)d_out;

    constexpr int SMEM64 = 1024 + 2 * (32768 + 64 * 256);    // 99328 (2 CTAs/SM)
    cudaFuncSetAttribute(tc_gemm<0>,
        cudaFuncAttributeMaxDynamicSharedMemorySize, SMEM64);
    cudaFuncSetAttribute(tc_gemm<1>,
        cudaFuncAttributeMaxDynamicSharedMemorySize, SMEM64);
    cudaFuncSetAttribute(tc_gemm<2>,
        cudaFuncAttributeMaxDynamicSharedMemorySize, SMEM64);

    void *p_xh, *p_xl, *p_wqh, *p_wql, *p_woh, *p_wol;
    void *p_qh, *p_ql, *p_attn, *p_ch, *p_cl, *p_vth, *p_vtl;
    void *p_u, *p_yh, *p_yl;
    cudaGetSymbolAddress(&p_xh,  g_xh);  cudaGetSymbolAddress(&p_xl,  g_xl);
    cudaGetSymbolAddress(&p_wqh, g_wqh); cudaGetSymbolAddress(&p_wql, g_wql);
    cudaGetSymbolAddress(&p_woh, g_woh); cudaGetSymbolAddress(&p_wol, g_wol);
    cudaGetSymbolAddress(&p_qh,  g_qkvh); cudaGetSymbolAddress(&p_ql, g_qkvl);
    cudaGetSymbolAddress(&p_attn, g_attn);
    cudaGetSymbolAddress(&p_ch,  g_ch);  cudaGetSymbolAddress(&p_cl,  g_cl);
    cudaGetSymbolAddress(&p_vth, g_vth); cudaGetSymbolAddress(&p_vtl, g_vtl);
    cudaGetSymbolAddress(&p_u,   g_u);
    cudaGetSymbolAddress(&p_yh,  g_yh);  cudaGetSymbolAddress(&p_yl,  g_yl);

    // 0) Operand conversions
    splitf_kernel<<<(KB * KN * KD) / 256, 256>>>(x, (bf16*)p_xh, (bf16*)p_xl,
                                                 KB * KN * KD);
    tsplit_kernel<<<dim3(KQ / 32, KD / 32), dim3(32, 8)>>>(
        w_qkv, (bf16*)p_wqh, (bf16*)p_wql, KD, KQ);
    tsplit_kernel<<<dim3(KD / 32, KD / 32), dim3(32, 8)>>>(
        w_out, (bf16*)p_woh, (bf16*)p_wol, KD, KD);

    // 1) QKV: [8192,1536] = x @ w_qkv  -> bf16 pair output
    tc_gemm<2><<<dim3(KQ / 64, (KB * KN) / 128, 1), 256, SMEM64>>>(
        (const bf16*)p_xh, (const bf16*)p_xl,
        (const bf16*)p_wqh, (const bf16*)p_wql,
        nullptr, (bf16*)p_qh, (bf16*)p_ql, nullptr,
        KD, KD, KD, KQ,
        1, 0, 0, 0, 0, 0, 0, 1.0f);

    // 2) Logits per (b,h): A = 0.125 * Q @ K^T -> fp32
    tc_gemm<0><<<dim3(KN / 64, KN / 128, KB * KH), 256, SMEM64>>>(
        (const bf16*)p_qh, (const bf16*)p_ql,
        (const bf16*)p_qh + 512, (const bf16*)p_ql + 512,
        (float*)p_attn, nullptr, nullptr, nullptr,
        KDH, KQ, KQ, KN,
        KH, (long)KN * KQ, 64, (long)KN * KQ, 64,
        (long)KH * KN * KN, (long)KN * KN, 0.125f);

    // 3) Fused softmax + conv head-mix (bf16 pair out) + cross moments
    smconv_kernel<<<KB * KN, 256>>>(conv_w);

    // 4) Stats path + V^T
    reduce_kernel<<<36, 256>>>();
    vsum_kernel<<<KB * KH, 256>>>();
    stats_kernel<<<1, 32>>>(conv_w, conv_b, gamma, beta);
    vtrans_kernel<<<dim3(KN / 32, KDH / 32, KB * KH), dim3(32, 8)>>>();

    // 5) U[b,h] = C[b,h] @ V[b,h]  (M=1024, N=64, K=1024) -> fp32
    tc_gemm<0><<<dim3(1, KN / 128, KB * KH), 256, SMEM64>>>(
        (const bf16*)p_ch, (const bf16*)p_cl,
        (const bf16*)p_vth, (const bf16*)p_vtl,
        (float*)p_u, nullptr, nullptr, nullptr,
        KN, KN, KN, KDH,
        KH, (long)KH * KN * KN, (long)KN * KN,
        (long)KH * KDH * KN, (long)KDH * KN,
        (long)KH * KN * KDH, (long)KN * KDH, 1.0f);

    // 6) Assemble Y (deferred BN affine) -> bf16 pair
    assemble_kernel<<<(KB * KN * KD) / 256, 256>>>();

    // 7) out = Y @ w_out + b_out
    tc_gemm<1><<<dim3(KD / 64, (KB * KN) / 128, 1), 256, SMEM64>>>(
        (const bf16*)p_yh, (const bf16*)p_yl,
        (const bf16*)p_woh, (const bf16*)p_wol,
        out, nullptr, nullptr, b_out,
        KD, KD, KD, KD,
        1, 0, 0, 0, 0, 0, 0, 1.0f);
}